// round 9
// baseline (speedup 1.0000x reference)
#include <cuda.h>
#include <cuda_runtime.h>
#include <cuda_fp16.h>
#include <cstdint>

#define N_NODES   100000
#define IN_FEATS  512
#define N_HIDDEN  1024
#define N_CLASSES 64
#define MAX_EDGES 1600000
#define K_ITERS   10
#define ALPHA_F   0.1f
#define NS 3

// ---------------- static device scratch ----------------
__device__ __align__(128) __half g_fh[(size_t)N_NODES * IN_FEATS];
__device__ __align__(128) __half g_h1h[(size_t)N_NODES * N_HIDDEN];
__device__ __align__(128) __half g_h2h[(size_t)N_NODES * N_HIDDEN];
__device__ __align__(128) __half g_w0[(size_t)N_HIDDEN * IN_FEATS];
__device__ __align__(128) __half g_w1[(size_t)N_HIDDEN * N_HIDDEN];
__device__ __align__(128) __half g_w2[(size_t)N_CLASSES * N_HIDDEN];
__device__ __align__(16) float  g_h0[(size_t)N_NODES * N_CLASSES];
__device__ __align__(128) __half g_hsA[(size_t)N_NODES * N_CLASSES];
__device__ __align__(128) __half g_hsB[(size_t)N_NODES * N_CLASSES];
__device__ __align__(16) float g_norm[N_NODES];
__device__ __align__(16) int   g_deg[N_NODES];
__device__ __align__(16) int   g_rowptr[N_NODES + 4];
__device__ __align__(16) int   g_fill[N_NODES];
__device__ __align__(16) int   g_col[MAX_EDGES];
__device__ int g_is64;
__device__ unsigned g_sync_count;   // zero-initialized; reset at kernel exit
__device__ unsigned g_sync_phase;   // zero-initialized; reset at kernel exit

// ---------------- PTX helpers (sm_90 baseline; no tcgen05) ----------------
__device__ __forceinline__ uint32_t smem_to_u32(const void* p) {
    uint32_t a;
    asm("{ .reg .u64 t; cvta.to.shared.u64 t, %1; cvt.u32.u64 %0, t; }" : "=r"(a) : "l"(p));
    return a;
}
#define MBARRIER_INIT(a, c) \
    asm volatile("mbarrier.init.shared.b64 [%0], %1;" :: "r"((uint32_t)(a)), "r"((uint32_t)(c)) : "memory")
#define MBARRIER_EXPECT_TX(a, b) \
    asm volatile("mbarrier.arrive.expect_tx.shared.b64 _, [%0], %1;" :: "r"((uint32_t)(a)), "r"((uint32_t)(b)) : "memory")
#define MBARRIER_WAIT_PARITY(a, ph) do { \
    uint32_t _m = (uint32_t)(a), _p = (uint32_t)(ph), _d; \
    asm volatile("{\n\t.reg .pred p;\n\tmbarrier.try_wait.parity.acquire.cta.shared::cta.b64 p, [%1], %2;\n\tselp.b32 %0, 1, 0, p;\n\t}" \
        : "=r"(_d) : "r"(_m), "r"(_p) : "memory"); \
    if (!_d) { \
        asm volatile("{\n\t.reg .pred P1;\n\tWL_%=:\n\tmbarrier.try_wait.parity.acquire.cta.shared::cta.b64 P1, [%0], %1, 0x989680;\n\t@P1 bra.uni WD_%=;\n\tbra.uni WL_%=;\n\tWD_%=:\n\t}" \
            :: "r"(_m), "r"(_p) : "memory"); \
    } \
} while (0)
#define TMA_LOAD_2D(sa, map, cx, cy, mb) \
    asm volatile("cp.async.bulk.tensor.2d.shared::cta.global.tile.mbarrier::complete_tx::bytes [%0], [%1, {%2, %3}], [%4];" \
        :: "r"((uint32_t)(sa)), "l"(map), "r"((int32_t)(cx)), "r"((int32_t)(cy)), "r"((uint32_t)(mb)) : "memory")
#define LDSM4(R0, R1, R2, R3, addr) \
    asm volatile("ldmatrix.sync.aligned.m8n8.x4.shared.b16 {%0,%1,%2,%3}, [%4];\n" \
                 : "=r"(R0), "=r"(R1), "=r"(R2), "=r"(R3) : "r"(addr))
#define MMAF16(D, A, B0, B1) \
    asm volatile("mma.sync.aligned.m16n8k16.row.col.f32.f16.f16.f32 " \
                 "{%0,%1,%2,%3}, {%4,%5,%6,%7}, {%8,%9}, {%0,%1,%2,%3};\n" \
                 : "+f"(D[0]), "+f"(D[1]), "+f"(D[2]), "+f"(D[3]) \
                 : "r"(A[0]), "r"(A[1]), "r"(A[2]), "r"(A[3]), "r"(B0), "r"(B1))

// ---------------- dtype sniff / CSR ----------------
__global__ void detect_kernel(const int* idx, int E) {
    __shared__ int s_nz;
    if (threadIdx.x == 0) s_nz = 0;
    __syncthreads();
    int lim = min(1024, E / 2), nz = 0;
    for (int i = threadIdx.x; i < lim; i += blockDim.x)
        nz += (idx[2 * i + 1] != 0) ? 1 : 0;
    atomicAdd(&s_nz, nz);
    __syncthreads();
    if (threadIdx.x == 0) g_is64 = (s_nz == 0) ? 1 : 0;
}
__device__ __forceinline__ int load_idx(const void* p, int i, int is64) {
    return is64 ? (int)((const long long*)p)[i] : ((const int*)p)[i];
}
__global__ void count_deg_kernel(const void* __restrict__ dst, int* __restrict__ deg, int E) {
    int e = blockIdx.x * blockDim.x + threadIdx.x;
    if (e >= E) return;
    atomicAdd(&deg[load_idx(dst, e, g_is64)], 1);
}
__global__ void scan_kernel(const int* __restrict__ deg, int* __restrict__ rowptr,
                            int* __restrict__ fill, float* __restrict__ norm,
                            int n, int total) {
    __shared__ int s[1024];
    int t = threadIdx.x;
    int chunk = (((n + 1023) >> 10) + 3) & ~3;
    int beg = min(t * chunk, n), end = min(beg + chunk, n);
    int sum = 0, i = beg;
    for (; i + 4 <= end; i += 4) {
        int4 d = *(const int4*)(deg + i);
        sum += d.x + d.y + d.z + d.w;
    }
    for (; i < end; i++) sum += deg[i];
    s[t] = sum;
    __syncthreads();
    for (int off = 1; off < 1024; off <<= 1) {
        int v = (t >= off) ? s[t - off] : 0;
        __syncthreads();
        s[t] += v;
        __syncthreads();
    }
    int run = (t == 0) ? 0 : s[t - 1];
    for (i = beg; i + 4 <= end; i += 4) {
        int4 d = *(const int4*)(deg + i);
        int4 r4;
        r4.x = run; r4.y = run + d.x; r4.z = r4.y + d.y; r4.w = r4.z + d.z;
        *(int4*)(rowptr + i) = r4;
        *(int4*)(fill + i) = r4;
        float4 n4;
        n4.x = rsqrtf(fmaxf((float)d.x, 1.0f));
        n4.y = rsqrtf(fmaxf((float)d.y, 1.0f));
        n4.z = rsqrtf(fmaxf((float)d.z, 1.0f));
        n4.w = rsqrtf(fmaxf((float)d.w, 1.0f));
        *(float4*)(norm + i) = n4;
        run = r4.w + d.w;
    }
    for (; i < end; i++) {
        rowptr[i] = run; fill[i] = run;
        int d = deg[i]; run += d;
        norm[i] = rsqrtf(fmaxf((float)d, 1.0f));
    }
    if (t == 0) rowptr[n] = total;
}
__global__ void fill_csr_kernel(const void* __restrict__ src, const void* __restrict__ dst,
                                int* __restrict__ fill, int* __restrict__ col, int E) {
    int e = blockIdx.x * blockDim.x + threadIdx.x;
    if (e >= E) return;
    int is64 = g_is64;
    int d = load_idx(dst, e, is64);
    int sv = load_idx(src, e, is64);
    col[atomicAdd(&fill[d], 1)] = sv;
}

// ---------------- conversion prepasses ----------------
__global__ void fconv_kernel(const float* __restrict__ x, __half* __restrict__ h, int n4) {
    int i = blockIdx.x * blockDim.x + threadIdx.x;
    if (i >= n4) return;
    float4 v = ((const float4*)x)[i];
    __half2 a = __floats2half2_rn(v.x, v.y);
    __half2 b = __floats2half2_rn(v.z, v.w);
    ((uint2*)h)[i] = make_uint2(*(uint32_t*)&a, *(uint32_t*)&b);
}
__global__ void wconv_kernel(const float* __restrict__ W, __half* __restrict__ Wt,
                             int K, int Nout) {
    int idx = blockIdx.x * blockDim.x + threadIdx.x;
    if (idx >= K * Nout) return;
    int k = idx / Nout, n = idx % Nout;
    Wt[(size_t)n * K + k] = __float2half_rn(W[idx]);
}

// ---------------- TMA + mma.sync fp16 GEMM: C = act(A @ Wt^T + bias) ----------------
template <int NFRAG, int OUT_HALF, int RELU, int WRITE_HS>
__global__ void __launch_bounds__(256, 2)
gemm_tma(const __grid_constant__ CUtensorMap mA, const __grid_constant__ CUtensorMap mB,
         const float* __restrict__ bias, float* __restrict__ Cf, __half* __restrict__ Ch,
         const float* __restrict__ normp, __half* __restrict__ Hs,
         int M, int K, int Nout) {
    constexpr int BN = NFRAG * 16;
    constexpr int WN = NFRAG * 8;
    constexpr int ABYT = 128 * 64 * 2;
    constexpr int BBYT = BN * 64 * 2;
    constexpr int STAGE = ABYT + BBYT;

    extern __shared__ __align__(1024) char dsm[];
    __shared__ __align__(8) unsigned long long s_bar[NS];

    const int tid = threadIdx.x, lane = tid & 31, wid = tid >> 5;
    const int wm = wid & 3, wn = wid >> 2;
    const int m0 = blockIdx.y * 128, n0 = blockIdx.x * BN;
    const uint32_t sb = smem_to_u32(dsm);
    const uint32_t bar = smem_to_u32(s_bar);
    const int NKT = K >> 6;

    if (tid == 0) {
#pragma unroll
        for (int i = 0; i < NS; i++) MBARRIER_INIT(bar + 8 * i, 1);
    }
    __syncthreads();

    if (tid == 0) {
        for (int s = 0; s < NS && s < NKT; s++) {
            uint32_t sa = sb + s * STAGE;
            uint32_t mb = bar + 8 * s;
            MBARRIER_EXPECT_TX(mb, (uint32_t)STAGE);
            TMA_LOAD_2D(sa, &mA, s * 64, m0, mb);
            TMA_LOAD_2D(sa + ABYT, &mB, s * 64, n0, mb);
        }
    }

    float acc[2][NFRAG][4];
#pragma unroll
    for (int a = 0; a < 2; a++)
#pragma unroll
        for (int b = 0; b < NFRAG; b++)
#pragma unroll
            for (int c = 0; c < 4; c++) acc[a][b][c] = 0.f;

    const int csel = (lane >> 4) << 3;
    const int rsub = lane & 15;

    for (int i = 0; i < NKT; i++) {
        int s = i - (i / NS) * NS;
        MBARRIER_WAIT_PARITY(bar + 8 * s, (i / NS) & 1);
        uint32_t aB = sb + s * STAGE;
        uint32_t bB = aB + ABYT;
#pragma unroll
        for (int kc = 0; kc < 4; kc++) {
            int cc = kc * 16 + csel;
            int chunk = cc >> 3;
            uint32_t a[2][4];
#pragma unroll
            for (int mt = 0; mt < 2; mt++) {
                int r = wm * 32 + mt * 16 + rsub;
                uint32_t off = (uint32_t)(r * 128 + ((chunk ^ (r & 7)) << 4));
                LDSM4(a[mt][0], a[mt][1], a[mt][2], a[mt][3], aB + off);
            }
            uint32_t bfr[NFRAG][2];
#pragma unroll
            for (int p = 0; p < NFRAG / 2; p++) {
                int r = wn * WN + p * 16 + rsub;
                uint32_t off = (uint32_t)(r * 128 + ((chunk ^ (r & 7)) << 4));
                uint32_t r0, r1, r2, r3;
                LDSM4(r0, r1, r2, r3, bB + off);
                bfr[2 * p][0] = r0; bfr[2 * p][1] = r2;
                bfr[2 * p + 1][0] = r1; bfr[2 * p + 1][1] = r3;
            }
#pragma unroll
            for (int mt = 0; mt < 2; mt++)
#pragma unroll
                for (int nt = 0; nt < NFRAG; nt++)
                    MMAF16(acc[mt][nt], a[mt], bfr[nt][0], bfr[nt][1]);
        }
        __syncthreads();
        if (tid == 0 && i + NS < NKT) {
            int kx = (i + NS) * 64;
            uint32_t sa = sb + s * STAGE;
            uint32_t mb = bar + 8 * s;
            MBARRIER_EXPECT_TX(mb, (uint32_t)STAGE);
            TMA_LOAD_2D(sa, &mA, kx, m0, mb);
            TMA_LOAD_2D(sa + ABYT, &mB, kx, n0, mb);
        }
    }

    // ---- epilogue ----
    const int g = lane >> 2, tq = (lane & 3) << 1;
#pragma unroll
    for (int mt = 0; mt < 2; mt++) {
        int r = m0 + wm * 32 + mt * 16 + g;
        float nn0 = 0.f, nn1 = 0.f;
        if (WRITE_HS) {
            if (r < M) nn0 = normp[r];
            if (r + 8 < M) nn1 = normp[r + 8];
        }
#pragma unroll
        for (int nt = 0; nt < NFRAG; nt++) {
            int cb = n0 + wn * WN + nt * 8 + tq;
            float b0v = __ldg(bias + cb), b1v = __ldg(bias + cb + 1);
            float v0 = acc[mt][nt][0] + b0v, v1 = acc[mt][nt][1] + b1v;
            float v2 = acc[mt][nt][2] + b0v, v3 = acc[mt][nt][3] + b1v;
            if (RELU) {
                v0 = fmaxf(v0, 0.f); v1 = fmaxf(v1, 0.f);
                v2 = fmaxf(v2, 0.f); v3 = fmaxf(v3, 0.f);
            }
            if (OUT_HALF) {
                if (r < M) {
                    __half2 hp = __floats2half2_rn(v0, v1);
                    *(uint32_t*)(Ch + (size_t)r * Nout + cb) = *(uint32_t*)&hp;
                }
                if (r + 8 < M) {
                    __half2 hp = __floats2half2_rn(v2, v3);
                    *(uint32_t*)(Ch + (size_t)(r + 8) * Nout + cb) = *(uint32_t*)&hp;
                }
            } else {
                if (r < M) {
                    *(float2*)(Cf + (size_t)r * Nout + cb) = make_float2(v0, v1);
                    if (WRITE_HS) {
                        __half2 hp = __floats2half2_rn(v0 * nn0, v1 * nn0);
                        *(uint32_t*)(Hs + (size_t)r * Nout + cb) = *(uint32_t*)&hp;
                    }
                }
                if (r + 8 < M) {
                    *(float2*)(Cf + (size_t)(r + 8) * Nout + cb) = make_float2(v2, v3);
                    if (WRITE_HS) {
                        __half2 hp = __floats2half2_rn(v2 * nn1, v3 * nn1);
                        *(uint32_t*)(Hs + (size_t)(r + 8) * Nout + cb) = *(uint32_t*)&hp;
                    }
                }
            }
        }
    }
}

// ---------------- persistent propagation: all K_ITERS in one kernel ----------------
// Software grid barrier (sense by monotonically increasing phase; reset at exit).
__device__ __forceinline__ void grid_sync(unsigned nblocks, unsigned target) {
    __threadfence();
    __syncthreads();
    if (threadIdx.x == 0) {
        unsigned v = atomicAdd(&g_sync_count, 1u);
        if (v == nblocks - 1u) {
            g_sync_count = 0u;
            __threadfence();
            *(volatile unsigned*)&g_sync_phase = target;
        } else {
            while (*(volatile unsigned*)&g_sync_phase < target) { }
        }
        __threadfence();
    }
    __syncthreads();
}

__global__ void __launch_bounds__(256)
prop_all_kernel(__half* __restrict__ bufA, __half* __restrict__ bufB,
                const float* __restrict__ h0, const float* __restrict__ norm,
                const int* __restrict__ rowptr, const int* __restrict__ col,
                float* __restrict__ outf, int n) {
    const unsigned nblocks = gridDim.x;
    const int lane = threadIdx.x & 31;
    const int sub = lane >> 3;   // node within warp's group of 4
    const int l8 = lane & 7;
    const int wglob = (int)((blockIdx.x * blockDim.x + threadIdx.x) >> 5);
    const int totalWarps = (int)((nblocks * blockDim.x) >> 5);
    const int ngroups = (n + 3) >> 2;

    const __half* cur = bufA;
    __half* nxt = bufB;

    for (int it = 0; it < K_ITERS; it++) {
        const int last = (it == K_ITERS - 1);
        for (int ng = wglob; ng < ngroups; ng += totalWarps) {
            int node = ng * 4 + sub;
            if (node >= n) continue;
            int beg = rowptr[node], end = rowptr[node + 1];
            float a0 = 0.f, a1 = 0.f, a2 = 0.f, a3 = 0.f;
            float a4 = 0.f, a5 = 0.f, a6 = 0.f, a7 = 0.f;
            int j = beg;
            for (; j + 2 <= end; j += 2) {
                int s0 = col[j], s1 = col[j + 1];
                uint4 v = *(const uint4*)(cur + (size_t)s0 * N_CLASSES + l8 * 8);
                uint4 w = *(const uint4*)(cur + (size_t)s1 * N_CLASSES + l8 * 8);
                float2 f0 = __half22float2(*(__half2*)&v.x);
                float2 f1 = __half22float2(*(__half2*)&v.y);
                float2 f2 = __half22float2(*(__half2*)&v.z);
                float2 f3 = __half22float2(*(__half2*)&v.w);
                float2 g0 = __half22float2(*(__half2*)&w.x);
                float2 g1 = __half22float2(*(__half2*)&w.y);
                float2 g2 = __half22float2(*(__half2*)&w.z);
                float2 g3 = __half22float2(*(__half2*)&w.w);
                a0 += f0.x + g0.x; a1 += f0.y + g0.y;
                a2 += f1.x + g1.x; a3 += f1.y + g1.y;
                a4 += f2.x + g2.x; a5 += f2.y + g2.y;
                a6 += f3.x + g3.x; a7 += f3.y + g3.y;
            }
            if (j < end) {
                uint4 v = *(const uint4*)(cur + (size_t)col[j] * N_CLASSES + l8 * 8);
                float2 f0 = __half22float2(*(__half2*)&v.x);
                float2 f1 = __half22float2(*(__half2*)&v.y);
                float2 f2 = __half22float2(*(__half2*)&v.z);
                float2 f3 = __half22float2(*(__half2*)&v.w);
                a0 += f0.x; a1 += f0.y; a2 += f1.x; a3 += f1.y;
                a4 += f2.x; a5 += f2.y; a6 += f3.x; a7 += f3.y;
            }
            float nn = norm[node];
            const float* hp = h0 + (size_t)node * N_CLASSES + l8 * 8;
            float4 hA = *(const float4*)hp;
            float4 hB = *(const float4*)(hp + 4);
            float o0 = (1.0f - ALPHA_F) * a0 * nn + ALPHA_F * hA.x;
            float o1 = (1.0f - ALPHA_F) * a1 * nn + ALPHA_F * hA.y;
            float o2 = (1.0f - ALPHA_F) * a2 * nn + ALPHA_F * hA.z;
            float o3 = (1.0f - ALPHA_F) * a3 * nn + ALPHA_F * hA.w;
            float o4 = (1.0f - ALPHA_F) * a4 * nn + ALPHA_F * hB.x;
            float o5 = (1.0f - ALPHA_F) * a5 * nn + ALPHA_F * hB.y;
            float o6 = (1.0f - ALPHA_F) * a6 * nn + ALPHA_F * hB.z;
            float o7 = (1.0f - ALPHA_F) * a7 * nn + ALPHA_F * hB.w;
            if (last) {
                float* op = outf + (size_t)node * N_CLASSES + l8 * 8;
                *(float4*)op = make_float4(o0, o1, o2, o3);
                *(float4*)(op + 4) = make_float4(o4, o5, o6, o7);
            } else {
                __half2 p0 = __floats2half2_rn(o0 * nn, o1 * nn);
                __half2 p1 = __floats2half2_rn(o2 * nn, o3 * nn);
                __half2 p2 = __floats2half2_rn(o4 * nn, o5 * nn);
                __half2 p3 = __floats2half2_rn(o6 * nn, o7 * nn);
                uint4 w = make_uint4(*(uint32_t*)&p0, *(uint32_t*)&p1,
                                     *(uint32_t*)&p2, *(uint32_t*)&p3);
                *(uint4*)(nxt + (size_t)node * N_CLASSES + l8 * 8) = w;
            }
        }
        if (!last) grid_sync(nblocks, (unsigned)(it + 1));
        __half* t = (__half*)cur; cur = nxt; nxt = t;
    }

    // exit reset (arrival only; no spin) so the next graph replay sees phase 0
    __syncthreads();
    if (threadIdx.x == 0) {
        unsigned v = atomicAdd(&g_sync_count, 1u);
        if (v == nblocks - 1u) {
            g_sync_count = 0u;
            __threadfence();
            *(volatile unsigned*)&g_sync_phase = 0u;
        }
    }
}

// ---------------- host: tensormap + launch ----------------
typedef CUresult (*EncodeFn)(CUtensorMap*, CUtensorMapDataType, cuuint32_t, void*,
                             const cuuint64_t*, const cuuint64_t*, const cuuint32_t*,
                             const cuuint32_t*, CUtensorMapInterleave, CUtensorMapSwizzle,
                             CUtensorMapL2promotion, CUtensorMapFloatOOBfill);

static void make_map(EncodeFn enc, CUtensorMap* m, void* base, uint64_t d0, uint64_t d1,
                     uint32_t b0, uint32_t b1) {
    cuuint64_t dims[2] = {d0, d1};
    cuuint64_t strides[1] = {d0 * 2};
    cuuint32_t box[2] = {b0, b1};
    cuuint32_t es[2] = {1, 1};
    enc(m, CU_TENSOR_MAP_DATA_TYPE_FLOAT16, 2, base, dims, strides, box, es,
        CU_TENSOR_MAP_INTERLEAVE_NONE, CU_TENSOR_MAP_SWIZZLE_128B,
        CU_TENSOR_MAP_L2_PROMOTION_L2_128B, CU_TENSOR_MAP_FLOAT_OOB_FILL_NONE);
}

extern "C" void kernel_launch(void* const* d_in, const int* in_sizes, int n_in,
                              void* d_out, int out_size) {
    const float* features = (const float*)d_in[0];
    const void*  src = d_in[1];
    const void*  dst = d_in[2];
    const float* W0 = (const float*)d_in[3];
    const float* b0 = (const float*)d_in[4];
    const float* W1 = (const float*)d_in[5];
    const float* b1 = (const float*)d_in[6];
    const float* W2 = (const float*)d_in[7];
    const float* b2 = (const float*)d_in[8];
    float* out = (float*)d_out;
    const int Nn = in_sizes[0] / IN_FEATS;
    const int E  = in_sizes[1];

    void *p_fh, *p_h1h, *p_h2h, *p_w0, *p_w1, *p_w2, *p_hsA, *p_hsB;
    float *p_h0, *p_norm;
    int *p_deg, *p_rowptr, *p_fill, *p_col;
    cudaGetSymbolAddress(&p_fh, g_fh);
    cudaGetSymbolAddress(&p_h1h, g_h1h);
    cudaGetSymbolAddress(&p_h2h, g_h2h);
    cudaGetSymbolAddress(&p_w0, g_w0);
    cudaGetSymbolAddress(&p_w1, g_w1);
    cudaGetSymbolAddress(&p_w2, g_w2);
    cudaGetSymbolAddress(&p_hsA, g_hsA);
    cudaGetSymbolAddress(&p_hsB, g_hsB);
    cudaGetSymbolAddress((void**)&p_h0, g_h0);
    cudaGetSymbolAddress((void**)&p_norm, g_norm);
    cudaGetSymbolAddress((void**)&p_deg, g_deg);
    cudaGetSymbolAddress((void**)&p_rowptr, g_rowptr);
    cudaGetSymbolAddress((void**)&p_fill, g_fill);
    cudaGetSymbolAddress((void**)&p_col, g_col);

    EncodeFn enc = nullptr;
    cudaDriverEntryPointQueryResult qst;
    cudaGetDriverEntryPointByVersion("cuTensorMapEncodeTiled", (void**)&enc, 12000,
                                     cudaEnableDefault, &qst);

    CUtensorMap mF, mH1, mH2, mW0, mW1, mW2;
    make_map(enc, &mF, p_fh, IN_FEATS, Nn, 64, 128);
    make_map(enc, &mH1, p_h1h, N_HIDDEN, Nn, 64, 128);
    make_map(enc, &mH2, p_h2h, N_HIDDEN, Nn, 64, 128);
    make_map(enc, &mW0, p_w0, IN_FEATS, N_HIDDEN, 64, 128);
    make_map(enc, &mW1, p_w1, N_HIDDEN, N_HIDDEN, 64, 128);
    make_map(enc, &mW2, p_w2, N_HIDDEN, N_CLASSES, 64, 64);

    // ---- side branch 1: CSR build; side branch 2: W1/W2 converts ----
    cudaStream_t side1, side2;
    cudaStreamCreate(&side1);
    cudaStreamCreate(&side2);
    cudaEvent_t evFork, evJoin1, evJoin2;
    cudaEventCreate(&evFork);
    cudaEventCreate(&evJoin1);
    cudaEventCreate(&evJoin2);
    cudaEventRecord(evFork, 0);
    cudaStreamWaitEvent(side1, evFork, 0);
    cudaStreamWaitEvent(side2, evFork, 0);

    detect_kernel<<<1, 256, 0, side1>>>((const int*)dst, E);
    cudaMemsetAsync(p_deg, 0, Nn * sizeof(int), side1);
    count_deg_kernel<<<(E + 255) / 256, 256, 0, side1>>>(dst, p_deg, E);
    scan_kernel<<<1, 1024, 0, side1>>>(p_deg, p_rowptr, p_fill, p_norm, Nn, E);
    fill_csr_kernel<<<(E + 255) / 256, 256, 0, side1>>>(src, dst, p_fill, p_col, E);
    cudaEventRecord(evJoin1, side1);

    wconv_kernel<<<(N_HIDDEN * N_HIDDEN + 255) / 256, 256, 0, side2>>>(
        W1, (__half*)p_w1, N_HIDDEN, N_HIDDEN);
    wconv_kernel<<<(N_HIDDEN * N_CLASSES + 255) / 256, 256, 0, side2>>>(
        W2, (__half*)p_w2, N_HIDDEN, N_CLASSES);
    cudaEventRecord(evJoin2, side2);

    // ---- main branch: feature/W0 converts + GEMM1 ----
    {
        int n4 = Nn * IN_FEATS / 4;
        fconv_kernel<<<(n4 + 255) / 256, 256>>>(features, (__half*)p_fh, n4);
        wconv_kernel<<<(IN_FEATS * N_HIDDEN + 255) / 256, 256>>>(
            W0, (__half*)p_w0, IN_FEATS, N_HIDDEN);
    }

    const int STG8 = 16384 + 128 * 64 * 2;   // 32768
    const int STG4 = 16384 + 64 * 64 * 2;    // 24576
    const int SM8 = NS * STG8;                // 98304 -> 2 CTAs/SM
    const int SM4 = NS * STG4;                // 73728
    cudaFuncSetAttribute(gemm_tma<8, 1, 1, 0>, cudaFuncAttributeMaxDynamicSharedMemorySize, SM8);
    cudaFuncSetAttribute(gemm_tma<4, 0, 0, 1>, cudaFuncAttributeMaxDynamicSharedMemorySize, SM4);

    int mtiles = (Nn + 127) / 128;
    {   // GEMM1: f -> h1 (relu, fp16 out)  [overlaps W1/W2 converts + CSR]
        dim3 grd(N_HIDDEN / 128, mtiles);
        gemm_tma<8, 1, 1, 0><<<grd, 256, SM8>>>(
            mF, mW0, b0, nullptr, (__half*)p_h1h, nullptr, nullptr, Nn, IN_FEATS, N_HIDDEN);
    }

    cudaStreamWaitEvent(0, evJoin2, 0);   // W1/W2 ready
    {   // GEMM2: h1 -> h2 (relu, fp16 out)
        dim3 grd(N_HIDDEN / 128, mtiles);
        gemm_tma<8, 1, 1, 0><<<grd, 256, SM8>>>(
            mH1, mW1, b1, nullptr, (__half*)p_h2h, nullptr, nullptr, Nn, N_HIDDEN, N_HIDDEN);
    }

    cudaStreamWaitEvent(0, evJoin1, 0);   // CSR + norm ready
    {   // GEMM3: h2 -> h0 fp32 + hs0 = h0*norm fp16 (fused init)
        dim3 grd(1, mtiles);
        gemm_tma<4, 0, 0, 1><<<grd, 256, SM4>>>(
            mH2, mW2, b2, p_h0, nullptr, p_norm, (__half*)p_hsA, Nn, N_HIDDEN, N_CLASSES);
    }

    // ---- persistent propagation: one kernel, K_ITERS iterations, grid barrier ----
    {
        int dev = 0;
        cudaGetDevice(&dev);
        int nsm = 148;
        cudaDeviceGetAttribute(&nsm, cudaDevAttrMultiProcessorCount, dev);
        int perSM = 1;
        cudaOccupancyMaxActiveBlocksPerMultiprocessor(&perSM, prop_all_kernel, 256, 0);
        if (perSM < 1) perSM = 1;
        int nb = nsm * perSM;
        // no need for more blocks than work groups
        int maxUseful = (Nn + 31) / 32;   // 8 warps/block, 4 nodes/warp
        if (nb > maxUseful) nb = maxUseful;
        prop_all_kernel<<<nb, 256>>>((__half*)p_hsA, (__half*)p_hsB, p_h0, p_norm,
                                     p_rowptr, p_col, out, Nn);
    }

    cudaEventDestroy(evFork);
    cudaEventDestroy(evJoin1);
    cudaEventDestroy(evJoin2);
    cudaStreamDestroy(side1);
    cudaStreamDestroy(side2);
}

// round 10
// speedup vs baseline: 1.0300x; 1.0300x over previous
#include <cuda.h>
#include <cuda_runtime.h>
#include <cuda_fp16.h>
#include <cstdint>

#define N_NODES   100000
#define IN_FEATS  512
#define N_HIDDEN  1024
#define N_CLASSES 64
#define MAX_EDGES 1600000
#define K_ITERS   10
#define ALPHA_F   0.1f
#define NS 3

// ---------------- static device scratch ----------------
__device__ __align__(128) __half g_fh[(size_t)N_NODES * IN_FEATS];
__device__ __align__(128) __half g_h1h[(size_t)N_NODES * N_HIDDEN];
__device__ __align__(128) __half g_h2h[(size_t)N_NODES * N_HIDDEN];
__device__ __align__(128) __half g_w0[(size_t)N_HIDDEN * IN_FEATS];
__device__ __align__(128) __half g_w1[(size_t)N_HIDDEN * N_HIDDEN];
__device__ __align__(128) __half g_w2[(size_t)N_CLASSES * N_HIDDEN];
__device__ __align__(16) float  g_h0[(size_t)N_NODES * N_CLASSES];
__device__ __align__(128) __half g_hsA[(size_t)N_NODES * N_CLASSES];
__device__ __align__(128) __half g_hsB[(size_t)N_NODES * N_CLASSES];
__device__ __align__(16) float g_norm[N_NODES];
__device__ __align__(16) int   g_deg[N_NODES];
__device__ __align__(16) int   g_rowptr[N_NODES + 4];
__device__ __align__(16) int   g_fill[N_NODES];
__device__ __align__(16) int   g_col[MAX_EDGES];
__device__ int g_is64;

// ---------------- PTX helpers (sm_90 baseline; no tcgen05) ----------------
__device__ __forceinline__ uint32_t smem_to_u32(const void* p) {
    uint32_t a;
    asm("{ .reg .u64 t; cvta.to.shared.u64 t, %1; cvt.u32.u64 %0, t; }" : "=r"(a) : "l"(p));
    return a;
}
#define MBARRIER_INIT(a, c) \
    asm volatile("mbarrier.init.shared.b64 [%0], %1;" :: "r"((uint32_t)(a)), "r"((uint32_t)(c)) : "memory")
#define MBARRIER_EXPECT_TX(a, b) \
    asm volatile("mbarrier.arrive.expect_tx.shared.b64 _, [%0], %1;" :: "r"((uint32_t)(a)), "r"((uint32_t)(b)) : "memory")
#define MBARRIER_WAIT_PARITY(a, ph) do { \
    uint32_t _m = (uint32_t)(a), _p = (uint32_t)(ph), _d; \
    asm volatile("{\n\t.reg .pred p;\n\tmbarrier.try_wait.parity.acquire.cta.shared::cta.b64 p, [%1], %2;\n\tselp.b32 %0, 1, 0, p;\n\t}" \
        : "=r"(_d) : "r"(_m), "r"(_p) : "memory"); \
    if (!_d) { \
        asm volatile("{\n\t.reg .pred P1;\n\tWL_%=:\n\tmbarrier.try_wait.parity.acquire.cta.shared::cta.b64 P1, [%0], %1, 0x989680;\n\t@P1 bra.uni WD_%=;\n\tbra.uni WL_%=;\n\tWD_%=:\n\t}" \
            :: "r"(_m), "r"(_p) : "memory"); \
    } \
} while (0)
#define TMA_LOAD_2D(sa, map, cx, cy, mb) \
    asm volatile("cp.async.bulk.tensor.2d.shared::cta.global.tile.mbarrier::complete_tx::bytes [%0], [%1, {%2, %3}], [%4];" \
        :: "r"((uint32_t)(sa)), "l"(map), "r"((int32_t)(cx)), "r"((int32_t)(cy)), "r"((uint32_t)(mb)) : "memory")
#define LDSM4(R0, R1, R2, R3, addr) \
    asm volatile("ldmatrix.sync.aligned.m8n8.x4.shared.b16 {%0,%1,%2,%3}, [%4];\n" \
                 : "=r"(R0), "=r"(R1), "=r"(R2), "=r"(R3) : "r"(addr))
#define MMAF16(D, A, B0, B1) \
    asm volatile("mma.sync.aligned.m16n8k16.row.col.f32.f16.f16.f32 " \
                 "{%0,%1,%2,%3}, {%4,%5,%6,%7}, {%8,%9}, {%0,%1,%2,%3};\n" \
                 : "+f"(D[0]), "+f"(D[1]), "+f"(D[2]), "+f"(D[3]) \
                 : "r"(A[0]), "r"(A[1]), "r"(A[2]), "r"(A[3]), "r"(B0), "r"(B1))

// ---------------- dtype sniff / CSR ----------------
__global__ void detect_kernel(const int* idx, int E) {
    __shared__ int s_nz;
    if (threadIdx.x == 0) s_nz = 0;
    __syncthreads();
    int lim = min(1024, E / 2), nz = 0;
    for (int i = threadIdx.x; i < lim; i += blockDim.x)
        nz += (idx[2 * i + 1] != 0) ? 1 : 0;
    atomicAdd(&s_nz, nz);
    __syncthreads();
    if (threadIdx.x == 0) g_is64 = (s_nz == 0) ? 1 : 0;
}
__device__ __forceinline__ int load_idx(const void* p, int i, int is64) {
    return is64 ? (int)((const long long*)p)[i] : ((const int*)p)[i];
}
__global__ void count_deg_kernel(const void* __restrict__ dst, int* __restrict__ deg, int E) {
    int e = blockIdx.x * blockDim.x + threadIdx.x;
    if (e >= E) return;
    atomicAdd(&deg[load_idx(dst, e, g_is64)], 1);
}
__global__ void scan_kernel(const int* __restrict__ deg, int* __restrict__ rowptr,
                            int* __restrict__ fill, float* __restrict__ norm,
                            int n, int total) {
    __shared__ int s[1024];
    int t = threadIdx.x;
    int chunk = (((n + 1023) >> 10) + 3) & ~3;
    int beg = min(t * chunk, n), end = min(beg + chunk, n);
    int sum = 0, i = beg;
    for (; i + 4 <= end; i += 4) {
        int4 d = *(const int4*)(deg + i);
        sum += d.x + d.y + d.z + d.w;
    }
    for (; i < end; i++) sum += deg[i];
    s[t] = sum;
    __syncthreads();
    for (int off = 1; off < 1024; off <<= 1) {
        int v = (t >= off) ? s[t - off] : 0;
        __syncthreads();
        s[t] += v;
        __syncthreads();
    }
    int run = (t == 0) ? 0 : s[t - 1];
    for (i = beg; i + 4 <= end; i += 4) {
        int4 d = *(const int4*)(deg + i);
        int4 r4;
        r4.x = run; r4.y = run + d.x; r4.z = r4.y + d.y; r4.w = r4.z + d.z;
        *(int4*)(rowptr + i) = r4;
        *(int4*)(fill + i) = r4;
        float4 n4;
        n4.x = rsqrtf(fmaxf((float)d.x, 1.0f));
        n4.y = rsqrtf(fmaxf((float)d.y, 1.0f));
        n4.z = rsqrtf(fmaxf((float)d.z, 1.0f));
        n4.w = rsqrtf(fmaxf((float)d.w, 1.0f));
        *(float4*)(norm + i) = n4;
        run = r4.w + d.w;
    }
    for (; i < end; i++) {
        rowptr[i] = run; fill[i] = run;
        int d = deg[i]; run += d;
        norm[i] = rsqrtf(fmaxf((float)d, 1.0f));
    }
    if (t == 0) rowptr[n] = total;
}
__global__ void fill_csr_kernel(const void* __restrict__ src, const void* __restrict__ dst,
                                int* __restrict__ fill, int* __restrict__ col, int E) {
    int e = blockIdx.x * blockDim.x + threadIdx.x;
    if (e >= E) return;
    int is64 = g_is64;
    int d = load_idx(dst, e, is64);
    int sv = load_idx(src, e, is64);
    col[atomicAdd(&fill[d], 1)] = sv;
}

// ---------------- conversion prepasses ----------------
__global__ void fconv_kernel(const float* __restrict__ x, __half* __restrict__ h, int n4) {
    int i = blockIdx.x * blockDim.x + threadIdx.x;
    if (i >= n4) return;
    float4 v = ((const float4*)x)[i];
    __half2 a = __floats2half2_rn(v.x, v.y);
    __half2 b = __floats2half2_rn(v.z, v.w);
    ((uint2*)h)[i] = make_uint2(*(uint32_t*)&a, *(uint32_t*)&b);
}
__global__ void wconv_kernel(const float* __restrict__ W, __half* __restrict__ Wt,
                             int K, int Nout) {
    int idx = blockIdx.x * blockDim.x + threadIdx.x;
    if (idx >= K * Nout) return;
    int k = idx / Nout, n = idx % Nout;
    Wt[(size_t)n * K + k] = __float2half_rn(W[idx]);
}

// ---------------- TMA + mma.sync fp16 GEMM: C = act(A @ Wt^T + bias) ----------------
template <int NFRAG, int OUT_HALF, int RELU, int WRITE_HS>
__global__ void __launch_bounds__(256, 2)
gemm_tma(const __grid_constant__ CUtensorMap mA, const __grid_constant__ CUtensorMap mB,
         const float* __restrict__ bias, float* __restrict__ Cf, __half* __restrict__ Ch,
         const float* __restrict__ normp, __half* __restrict__ Hs,
         int M, int K, int Nout) {
    constexpr int BN = NFRAG * 16;
    constexpr int WN = NFRAG * 8;
    constexpr int ABYT = 128 * 64 * 2;
    constexpr int BBYT = BN * 64 * 2;
    constexpr int STAGE = ABYT + BBYT;

    extern __shared__ __align__(1024) char dsm[];
    __shared__ __align__(8) unsigned long long s_bar[NS];

    const int tid = threadIdx.x, lane = tid & 31, wid = tid >> 5;
    const int wm = wid & 3, wn = wid >> 2;
    const int m0 = blockIdx.y * 128, n0 = blockIdx.x * BN;
    const uint32_t sb = smem_to_u32(dsm);
    const uint32_t bar = smem_to_u32(s_bar);
    const int NKT = K >> 6;

    if (tid == 0) {
#pragma unroll
        for (int i = 0; i < NS; i++) MBARRIER_INIT(bar + 8 * i, 1);
    }
    __syncthreads();

    if (tid == 0) {
        for (int s = 0; s < NS && s < NKT; s++) {
            uint32_t sa = sb + s * STAGE;
            uint32_t mb = bar + 8 * s;
            MBARRIER_EXPECT_TX(mb, (uint32_t)STAGE);
            TMA_LOAD_2D(sa, &mA, s * 64, m0, mb);
            TMA_LOAD_2D(sa + ABYT, &mB, s * 64, n0, mb);
        }
    }

    float acc[2][NFRAG][4];
#pragma unroll
    for (int a = 0; a < 2; a++)
#pragma unroll
        for (int b = 0; b < NFRAG; b++)
#pragma unroll
            for (int c = 0; c < 4; c++) acc[a][b][c] = 0.f;

    const int csel = (lane >> 4) << 3;
    const int rsub = lane & 15;

    for (int i = 0; i < NKT; i++) {
        int s = i - (i / NS) * NS;
        MBARRIER_WAIT_PARITY(bar + 8 * s, (i / NS) & 1);
        uint32_t aB = sb + s * STAGE;
        uint32_t bB = aB + ABYT;
#pragma unroll
        for (int kc = 0; kc < 4; kc++) {
            int cc = kc * 16 + csel;
            int chunk = cc >> 3;
            uint32_t a[2][4];
#pragma unroll
            for (int mt = 0; mt < 2; mt++) {
                int r = wm * 32 + mt * 16 + rsub;
                uint32_t off = (uint32_t)(r * 128 + ((chunk ^ (r & 7)) << 4));
                LDSM4(a[mt][0], a[mt][1], a[mt][2], a[mt][3], aB + off);
            }
            uint32_t bfr[NFRAG][2];
#pragma unroll
            for (int p = 0; p < NFRAG / 2; p++) {
                int r = wn * WN + p * 16 + rsub;
                uint32_t off = (uint32_t)(r * 128 + ((chunk ^ (r & 7)) << 4));
                uint32_t r0, r1, r2, r3;
                LDSM4(r0, r1, r2, r3, bB + off);
                bfr[2 * p][0] = r0; bfr[2 * p][1] = r2;
                bfr[2 * p + 1][0] = r1; bfr[2 * p + 1][1] = r3;
            }
#pragma unroll
            for (int mt = 0; mt < 2; mt++)
#pragma unroll
                for (int nt = 0; nt < NFRAG; nt++)
                    MMAF16(acc[mt][nt], a[mt], bfr[nt][0], bfr[nt][1]);
        }
        __syncthreads();
        if (tid == 0 && i + NS < NKT) {
            int kx = (i + NS) * 64;
            uint32_t sa = sb + s * STAGE;
            uint32_t mb = bar + 8 * s;
            MBARRIER_EXPECT_TX(mb, (uint32_t)STAGE);
            TMA_LOAD_2D(sa, &mA, kx, m0, mb);
            TMA_LOAD_2D(sa + ABYT, &mB, kx, n0, mb);
        }
    }

    // ---- epilogue ----
    const int g = lane >> 2, tq = (lane & 3) << 1;
#pragma unroll
    for (int mt = 0; mt < 2; mt++) {
        int r = m0 + wm * 32 + mt * 16 + g;
        float nn0 = 0.f, nn1 = 0.f;
        if (WRITE_HS) {
            if (r < M) nn0 = normp[r];
            if (r + 8 < M) nn1 = normp[r + 8];
        }
#pragma unroll
        for (int nt = 0; nt < NFRAG; nt++) {
            int cb = n0 + wn * WN + nt * 8 + tq;
            float b0v = __ldg(bias + cb), b1v = __ldg(bias + cb + 1);
            float v0 = acc[mt][nt][0] + b0v, v1 = acc[mt][nt][1] + b1v;
            float v2 = acc[mt][nt][2] + b0v, v3 = acc[mt][nt][3] + b1v;
            if (RELU) {
                v0 = fmaxf(v0, 0.f); v1 = fmaxf(v1, 0.f);
                v2 = fmaxf(v2, 0.f); v3 = fmaxf(v3, 0.f);
            }
            if (OUT_HALF) {
                if (r < M) {
                    __half2 hp = __floats2half2_rn(v0, v1);
                    *(uint32_t*)(Ch + (size_t)r * Nout + cb) = *(uint32_t*)&hp;
                }
                if (r + 8 < M) {
                    __half2 hp = __floats2half2_rn(v2, v3);
                    *(uint32_t*)(Ch + (size_t)(r + 8) * Nout + cb) = *(uint32_t*)&hp;
                }
            } else {
                if (r < M) {
                    *(float2*)(Cf + (size_t)r * Nout + cb) = make_float2(v0, v1);
                    if (WRITE_HS) {
                        __half2 hp = __floats2half2_rn(v0 * nn0, v1 * nn0);
                        *(uint32_t*)(Hs + (size_t)r * Nout + cb) = *(uint32_t*)&hp;
                    }
                }
                if (r + 8 < M) {
                    *(float2*)(Cf + (size_t)(r + 8) * Nout + cb) = make_float2(v2, v3);
                    if (WRITE_HS) {
                        __half2 hp = __floats2half2_rn(v2 * nn1, v3 * nn1);
                        *(uint32_t*)(Hs + (size_t)(r + 8) * Nout + cb) = *(uint32_t*)&hp;
                    }
                }
            }
        }
    }
}

// ---------------- propagation (fp16 state, per-iteration launches) ----------------
// 4 nodes per warp: 8 lanes per node, lane owns 8 classes (uint4 = 128b).
__global__ void prop_kernel(const __half* __restrict__ hs, const float* __restrict__ h0,
                            const float* __restrict__ norm, const int* __restrict__ rowptr,
                            const int* __restrict__ col, __half* __restrict__ outh,
                            float* __restrict__ outf, int n, int last) {
    int gt = blockIdx.x * blockDim.x + threadIdx.x;
    int lane = threadIdx.x & 31;
    int node = ((gt >> 5) << 2) + (lane >> 3);
    if (node >= n) return;
    int l8 = lane & 7;
    int beg = __ldg(rowptr + node), end = __ldg(rowptr + node + 1);
    float a0 = 0.f, a1 = 0.f, a2 = 0.f, a3 = 0.f, a4 = 0.f, a5 = 0.f, a6 = 0.f, a7 = 0.f;
    int j = beg;
    for (; j + 2 <= end; j += 2) {
        int s0 = __ldg(col + j), s1 = __ldg(col + j + 1);
        uint4 v = __ldg((const uint4*)(hs + (size_t)s0 * N_CLASSES + l8 * 8));
        uint4 w = __ldg((const uint4*)(hs + (size_t)s1 * N_CLASSES + l8 * 8));
        float2 f0 = __half22float2(*(__half2*)&v.x);
        float2 f1 = __half22float2(*(__half2*)&v.y);
        float2 f2 = __half22float2(*(__half2*)&v.z);
        float2 f3 = __half22float2(*(__half2*)&v.w);
        float2 g0 = __half22float2(*(__half2*)&w.x);
        float2 g1 = __half22float2(*(__half2*)&w.y);
        float2 g2 = __half22float2(*(__half2*)&w.z);
        float2 g3 = __half22float2(*(__half2*)&w.w);
        a0 += f0.x + g0.x; a1 += f0.y + g0.y;
        a2 += f1.x + g1.x; a3 += f1.y + g1.y;
        a4 += f2.x + g2.x; a5 += f2.y + g2.y;
        a6 += f3.x + g3.x; a7 += f3.y + g3.y;
    }
    if (j < end) {
        uint4 v = __ldg((const uint4*)(hs + (size_t)__ldg(col + j) * N_CLASSES + l8 * 8));
        float2 f0 = __half22float2(*(__half2*)&v.x);
        float2 f1 = __half22float2(*(__half2*)&v.y);
        float2 f2 = __half22float2(*(__half2*)&v.z);
        float2 f3 = __half22float2(*(__half2*)&v.w);
        a0 += f0.x; a1 += f0.y; a2 += f1.x; a3 += f1.y;
        a4 += f2.x; a5 += f2.y; a6 += f3.x; a7 += f3.y;
    }
    float nn = norm[node];
    const float* hp = h0 + (size_t)node * N_CLASSES + l8 * 8;
    float4 hA = *(const float4*)hp;
    float4 hB = *(const float4*)(hp + 4);
    float o0 = (1.0f - ALPHA_F) * a0 * nn + ALPHA_F * hA.x;
    float o1 = (1.0f - ALPHA_F) * a1 * nn + ALPHA_F * hA.y;
    float o2 = (1.0f - ALPHA_F) * a2 * nn + ALPHA_F * hA.z;
    float o3 = (1.0f - ALPHA_F) * a3 * nn + ALPHA_F * hA.w;
    float o4 = (1.0f - ALPHA_F) * a4 * nn + ALPHA_F * hB.x;
    float o5 = (1.0f - ALPHA_F) * a5 * nn + ALPHA_F * hB.y;
    float o6 = (1.0f - ALPHA_F) * a6 * nn + ALPHA_F * hB.z;
    float o7 = (1.0f - ALPHA_F) * a7 * nn + ALPHA_F * hB.w;
    if (last) {
        float* op = outf + (size_t)node * N_CLASSES + l8 * 8;
        *(float4*)op = make_float4(o0, o1, o2, o3);
        *(float4*)(op + 4) = make_float4(o4, o5, o6, o7);
    } else {
        __half2 p0 = __floats2half2_rn(o0 * nn, o1 * nn);
        __half2 p1 = __floats2half2_rn(o2 * nn, o3 * nn);
        __half2 p2 = __floats2half2_rn(o4 * nn, o5 * nn);
        __half2 p3 = __floats2half2_rn(o6 * nn, o7 * nn);
        uint4 w = make_uint4(*(uint32_t*)&p0, *(uint32_t*)&p1,
                             *(uint32_t*)&p2, *(uint32_t*)&p3);
        *(uint4*)(outh + (size_t)node * N_CLASSES + l8 * 8) = w;
    }
}

// ---------------- host: tensormap + launch ----------------
typedef CUresult (*EncodeFn)(CUtensorMap*, CUtensorMapDataType, cuuint32_t, void*,
                             const cuuint64_t*, const cuuint64_t*, const cuuint32_t*,
                             const cuuint32_t*, CUtensorMapInterleave, CUtensorMapSwizzle,
                             CUtensorMapL2promotion, CUtensorMapFloatOOBfill);

static void make_map(EncodeFn enc, CUtensorMap* m, void* base, uint64_t d0, uint64_t d1,
                     uint32_t b0, uint32_t b1) {
    cuuint64_t dims[2] = {d0, d1};
    cuuint64_t strides[1] = {d0 * 2};
    cuuint32_t box[2] = {b0, b1};
    cuuint32_t es[2] = {1, 1};
    enc(m, CU_TENSOR_MAP_DATA_TYPE_FLOAT16, 2, base, dims, strides, box, es,
        CU_TENSOR_MAP_INTERLEAVE_NONE, CU_TENSOR_MAP_SWIZZLE_128B,
        CU_TENSOR_MAP_L2_PROMOTION_L2_128B, CU_TENSOR_MAP_FLOAT_OOB_FILL_NONE);
}

extern "C" void kernel_launch(void* const* d_in, const int* in_sizes, int n_in,
                              void* d_out, int out_size) {
    const float* features = (const float*)d_in[0];
    const void*  src = d_in[1];
    const void*  dst = d_in[2];
    const float* W0 = (const float*)d_in[3];
    const float* b0 = (const float*)d_in[4];
    const float* W1 = (const float*)d_in[5];
    const float* b1 = (const float*)d_in[6];
    const float* W2 = (const float*)d_in[7];
    const float* b2 = (const float*)d_in[8];
    float* out = (float*)d_out;
    const int Nn = in_sizes[0] / IN_FEATS;
    const int E  = in_sizes[1];

    void *p_fh, *p_h1h, *p_h2h, *p_w0, *p_w1, *p_w2, *p_hsA, *p_hsB;
    float *p_h0, *p_norm;
    int *p_deg, *p_rowptr, *p_fill, *p_col;
    cudaGetSymbolAddress(&p_fh, g_fh);
    cudaGetSymbolAddress(&p_h1h, g_h1h);
    cudaGetSymbolAddress(&p_h2h, g_h2h);
    cudaGetSymbolAddress(&p_w0, g_w0);
    cudaGetSymbolAddress(&p_w1, g_w1);
    cudaGetSymbolAddress(&p_w2, g_w2);
    cudaGetSymbolAddress(&p_hsA, g_hsA);
    cudaGetSymbolAddress(&p_hsB, g_hsB);
    cudaGetSymbolAddress((void**)&p_h0, g_h0);
    cudaGetSymbolAddress((void**)&p_norm, g_norm);
    cudaGetSymbolAddress((void**)&p_deg, g_deg);
    cudaGetSymbolAddress((void**)&p_rowptr, g_rowptr);
    cudaGetSymbolAddress((void**)&p_fill, g_fill);
    cudaGetSymbolAddress((void**)&p_col, g_col);

    EncodeFn enc = nullptr;
    cudaDriverEntryPointQueryResult qst;
    cudaGetDriverEntryPointByVersion("cuTensorMapEncodeTiled", (void**)&enc, 12000,
                                     cudaEnableDefault, &qst);

    CUtensorMap mF, mH1, mH2, mW0, mW1, mW2;
    make_map(enc, &mF, p_fh, IN_FEATS, Nn, 64, 128);
    make_map(enc, &mH1, p_h1h, N_HIDDEN, Nn, 64, 128);
    make_map(enc, &mH2, p_h2h, N_HIDDEN, Nn, 64, 128);
    make_map(enc, &mW0, p_w0, IN_FEATS, N_HIDDEN, 64, 128);
    make_map(enc, &mW1, p_w1, N_HIDDEN, N_HIDDEN, 64, 128);
    make_map(enc, &mW2, p_w2, N_HIDDEN, N_CLASSES, 64, 64);

    // ---- side branch 1: CSR build; side branch 2: W1/W2 converts ----
    cudaStream_t side1, side2;
    cudaStreamCreate(&side1);
    cudaStreamCreate(&side2);
    cudaEvent_t evFork, evJoin1, evJoin2;
    cudaEventCreate(&evFork);
    cudaEventCreate(&evJoin1);
    cudaEventCreate(&evJoin2);
    cudaEventRecord(evFork, 0);
    cudaStreamWaitEvent(side1, evFork, 0);
    cudaStreamWaitEvent(side2, evFork, 0);

    detect_kernel<<<1, 256, 0, side1>>>((const int*)dst, E);
    cudaMemsetAsync(p_deg, 0, Nn * sizeof(int), side1);
    count_deg_kernel<<<(E + 255) / 256, 256, 0, side1>>>(dst, p_deg, E);
    scan_kernel<<<1, 1024, 0, side1>>>(p_deg, p_rowptr, p_fill, p_norm, Nn, E);
    fill_csr_kernel<<<(E + 255) / 256, 256, 0, side1>>>(src, dst, p_fill, p_col, E);
    cudaEventRecord(evJoin1, side1);

    wconv_kernel<<<(N_HIDDEN * N_HIDDEN + 255) / 256, 256, 0, side2>>>(
        W1, (__half*)p_w1, N_HIDDEN, N_HIDDEN);
    wconv_kernel<<<(N_HIDDEN * N_CLASSES + 255) / 256, 256, 0, side2>>>(
        W2, (__half*)p_w2, N_HIDDEN, N_CLASSES);
    cudaEventRecord(evJoin2, side2);

    // ---- main branch: feature/W0 converts + GEMM1 ----
    {
        int n4 = Nn * IN_FEATS / 4;
        fconv_kernel<<<(n4 + 255) / 256, 256>>>(features, (__half*)p_fh, n4);
        wconv_kernel<<<(IN_FEATS * N_HIDDEN + 255) / 256, 256>>>(
            W0, (__half*)p_w0, IN_FEATS, N_HIDDEN);
    }

    const int STG8 = 16384 + 128 * 64 * 2;   // 32768
    const int STG4 = 16384 + 64 * 64 * 2;    // 24576
    const int SM8 = NS * STG8;                // 98304 -> 2 CTAs/SM
    const int SM4 = NS * STG4;                // 73728
    cudaFuncSetAttribute(gemm_tma<8, 1, 1, 0>, cudaFuncAttributeMaxDynamicSharedMemorySize, SM8);
    cudaFuncSetAttribute(gemm_tma<4, 0, 0, 1>, cudaFuncAttributeMaxDynamicSharedMemorySize, SM4);

    int mtiles = (Nn + 127) / 128;
    {   // GEMM1: f -> h1 (relu, fp16 out)  [overlaps W1/W2 converts + CSR]
        dim3 grd(N_HIDDEN / 128, mtiles);
        gemm_tma<8, 1, 1, 0><<<grd, 256, SM8>>>(
            mF, mW0, b0, nullptr, (__half*)p_h1h, nullptr, nullptr, Nn, IN_FEATS, N_HIDDEN);
    }

    cudaStreamWaitEvent(0, evJoin2, 0);   // W1/W2 ready
    {   // GEMM2: h1 -> h2 (relu, fp16 out)
        dim3 grd(N_HIDDEN / 128, mtiles);
        gemm_tma<8, 1, 1, 0><<<grd, 256, SM8>>>(
            mH1, mW1, b1, nullptr, (__half*)p_h2h, nullptr, nullptr, Nn, N_HIDDEN, N_HIDDEN);
    }

    cudaStreamWaitEvent(0, evJoin1, 0);   // CSR + norm ready
    {   // GEMM3: h2 -> h0 fp32 + hs0 = h0*norm fp16 (fused init)
        dim3 grd(1, mtiles);
        gemm_tma<4, 0, 0, 1><<<grd, 256, SM4>>>(
            mH2, mW2, b2, p_h0, nullptr, p_norm, (__half*)p_hsA, Nn, N_HIDDEN, N_CLASSES);
    }

    // ---- propagation: per-iteration launches (fastest measured config) ----
    const __half* cur = (const __half*)p_hsA;
    for (int it = 0; it < K_ITERS; it++) {
        int last = (it == K_ITERS - 1) ? 1 : 0;
        __half* oh = (it & 1) ? (__half*)p_hsA : (__half*)p_hsB;
        int blocks = (Nn * 8 + 255) / 256;
        prop_kernel<<<blocks, 256>>>(cur, p_h0, p_norm, p_rowptr, p_col, oh, out, Nn, last);
        cur = oh;
    }

    cudaEventDestroy(evFork);
    cudaEventDestroy(evJoin1);
    cudaEventDestroy(evJoin2);
    cudaStreamDestroy(side1);
    cudaStreamDestroy(side2);
}

// round 11
// speedup vs baseline: 1.0453x; 1.0148x over previous
#include <cuda.h>
#include <cuda_runtime.h>
#include <cuda_fp16.h>
#include <cstdint>

#define N_NODES   100000
#define IN_FEATS  512
#define N_HIDDEN  1024
#define N_CLASSES 64
#define MAX_EDGES 1600000
#define K_ITERS   10
#define ALPHA_F   0.1f
#define NS 3

// ---------------- static device scratch ----------------
__device__ __align__(128) __half g_fh[(size_t)N_NODES * IN_FEATS];
__device__ __align__(128) __half g_h1h[(size_t)N_NODES * N_HIDDEN];
__device__ __align__(128) __half g_h2h[(size_t)N_NODES * N_HIDDEN];
__device__ __align__(128) __half g_w0[(size_t)N_HIDDEN * IN_FEATS];
__device__ __align__(128) __half g_w1[(size_t)N_HIDDEN * N_HIDDEN];
__device__ __align__(128) __half g_w2[(size_t)N_CLASSES * N_HIDDEN];
__device__ __align__(16) float  g_h0[(size_t)N_NODES * N_CLASSES];
__device__ __align__(128) __half g_hsA[(size_t)N_NODES * N_CLASSES];
__device__ __align__(128) __half g_hsB[(size_t)N_NODES * N_CLASSES];
__device__ __align__(16) float g_norm[N_NODES];
__device__ __align__(16) int   g_deg[N_NODES];
__device__ __align__(16) int   g_rowptr[N_NODES + 4];
__device__ __align__(16) int   g_fill[N_NODES];
__device__ __align__(16) int   g_col[MAX_EDGES];
__device__ int g_is64;

// ---------------- PTX helpers (sm_90 baseline; no tcgen05) ----------------
__device__ __forceinline__ uint32_t smem_to_u32(const void* p) {
    uint32_t a;
    asm("{ .reg .u64 t; cvta.to.shared.u64 t, %1; cvt.u32.u64 %0, t; }" : "=r"(a) : "l"(p));
    return a;
}
#define MBARRIER_INIT(a, c) \
    asm volatile("mbarrier.init.shared.b64 [%0], %1;" :: "r"((uint32_t)(a)), "r"((uint32_t)(c)) : "memory")
#define MBARRIER_EXPECT_TX(a, b) \
    asm volatile("mbarrier.arrive.expect_tx.shared.b64 _, [%0], %1;" :: "r"((uint32_t)(a)), "r"((uint32_t)(b)) : "memory")
#define MBARRIER_WAIT_PARITY(a, ph) do { \
    uint32_t _m = (uint32_t)(a), _p = (uint32_t)(ph), _d; \
    asm volatile("{\n\t.reg .pred p;\n\tmbarrier.try_wait.parity.acquire.cta.shared::cta.b64 p, [%1], %2;\n\tselp.b32 %0, 1, 0, p;\n\t}" \
        : "=r"(_d) : "r"(_m), "r"(_p) : "memory"); \
    if (!_d) { \
        asm volatile("{\n\t.reg .pred P1;\n\tWL_%=:\n\tmbarrier.try_wait.parity.acquire.cta.shared::cta.b64 P1, [%0], %1, 0x989680;\n\t@P1 bra.uni WD_%=;\n\tbra.uni WL_%=;\n\tWD_%=:\n\t}" \
            :: "r"(_m), "r"(_p) : "memory"); \
    } \
} while (0)
#define TMA_LOAD_2D(sa, map, cx, cy, mb) \
    asm volatile("cp.async.bulk.tensor.2d.shared::cta.global.tile.mbarrier::complete_tx::bytes [%0], [%1, {%2, %3}], [%4];" \
        :: "r"((uint32_t)(sa)), "l"(map), "r"((int32_t)(cx)), "r"((int32_t)(cy)), "r"((uint32_t)(mb)) : "memory")
#define LDSM4(R0, R1, R2, R3, addr) \
    asm volatile("ldmatrix.sync.aligned.m8n8.x4.shared.b16 {%0,%1,%2,%3}, [%4];\n" \
                 : "=r"(R0), "=r"(R1), "=r"(R2), "=r"(R3) : "r"(addr))
#define MMAF16(D, A, B0, B1) \
    asm volatile("mma.sync.aligned.m16n8k16.row.col.f32.f16.f16.f32 " \
                 "{%0,%1,%2,%3}, {%4,%5,%6,%7}, {%8,%9}, {%0,%1,%2,%3};\n" \
                 : "+f"(D[0]), "+f"(D[1]), "+f"(D[2]), "+f"(D[3]) \
                 : "r"(A[0]), "r"(A[1]), "r"(A[2]), "r"(A[3]), "r"(B0), "r"(B1))

// ---------------- dtype sniff / CSR ----------------
__global__ void detect_kernel(const int* idx, int E) {
    __shared__ int s_nz;
    if (threadIdx.x == 0) s_nz = 0;
    __syncthreads();
    int lim = min(1024, E / 2), nz = 0;
    for (int i = threadIdx.x; i < lim; i += blockDim.x)
        nz += (idx[2 * i + 1] != 0) ? 1 : 0;
    atomicAdd(&s_nz, nz);
    __syncthreads();
    if (threadIdx.x == 0) g_is64 = (s_nz == 0) ? 1 : 0;
}
__device__ __forceinline__ int load_idx(const void* p, int i, int is64) {
    return is64 ? (int)((const long long*)p)[i] : ((const int*)p)[i];
}
__global__ void count_deg_kernel(const void* __restrict__ dst, int* __restrict__ deg, int E) {
    int e = blockIdx.x * blockDim.x + threadIdx.x;
    if (e >= E) return;
    atomicAdd(&deg[load_idx(dst, e, g_is64)], 1);
}
__global__ void scan_kernel(const int* __restrict__ deg, int* __restrict__ rowptr,
                            int* __restrict__ fill, float* __restrict__ norm,
                            int n, int total) {
    __shared__ int s[1024];
    int t = threadIdx.x;
    int chunk = (((n + 1023) >> 10) + 3) & ~3;
    int beg = min(t * chunk, n), end = min(beg + chunk, n);
    int sum = 0, i = beg;
    for (; i + 4 <= end; i += 4) {
        int4 d = *(const int4*)(deg + i);
        sum += d.x + d.y + d.z + d.w;
    }
    for (; i < end; i++) sum += deg[i];
    s[t] = sum;
    __syncthreads();
    for (int off = 1; off < 1024; off <<= 1) {
        int v = (t >= off) ? s[t - off] : 0;
        __syncthreads();
        s[t] += v;
        __syncthreads();
    }
    int run = (t == 0) ? 0 : s[t - 1];
    for (i = beg; i + 4 <= end; i += 4) {
        int4 d = *(const int4*)(deg + i);
        int4 r4;
        r4.x = run; r4.y = run + d.x; r4.z = r4.y + d.y; r4.w = r4.z + d.z;
        *(int4*)(rowptr + i) = r4;
        *(int4*)(fill + i) = r4;
        float4 n4;
        n4.x = rsqrtf(fmaxf((float)d.x, 1.0f));
        n4.y = rsqrtf(fmaxf((float)d.y, 1.0f));
        n4.z = rsqrtf(fmaxf((float)d.z, 1.0f));
        n4.w = rsqrtf(fmaxf((float)d.w, 1.0f));
        *(float4*)(norm + i) = n4;
        run = r4.w + d.w;
    }
    for (; i < end; i++) {
        rowptr[i] = run; fill[i] = run;
        int d = deg[i]; run += d;
        norm[i] = rsqrtf(fmaxf((float)d, 1.0f));
    }
    if (t == 0) rowptr[n] = total;
}
__global__ void fill_csr_kernel(const void* __restrict__ src, const void* __restrict__ dst,
                                int* __restrict__ fill, int* __restrict__ col, int E) {
    int e = blockIdx.x * blockDim.x + threadIdx.x;
    if (e >= E) return;
    int is64 = g_is64;
    int d = load_idx(dst, e, is64);
    int sv = load_idx(src, e, is64);
    col[atomicAdd(&fill[d], 1)] = sv;
}

// ---------------- conversion prepasses ----------------
__global__ void fconv_kernel(const float* __restrict__ x, __half* __restrict__ h, int n4) {
    int i = blockIdx.x * blockDim.x + threadIdx.x;
    if (i >= n4) return;
    float4 v = ((const float4*)x)[i];
    __half2 a = __floats2half2_rn(v.x, v.y);
    __half2 b = __floats2half2_rn(v.z, v.w);
    ((uint2*)h)[i] = make_uint2(*(uint32_t*)&a, *(uint32_t*)&b);
}
__global__ void wconv_kernel(const float* __restrict__ W, __half* __restrict__ Wt,
                             int K, int Nout) {
    int idx = blockIdx.x * blockDim.x + threadIdx.x;
    if (idx >= K * Nout) return;
    int k = idx / Nout, n = idx % Nout;
    Wt[(size_t)n * K + k] = __float2half_rn(W[idx]);
}

// ---------------- TMA + mma.sync fp16 GEMM: C = act(A @ Wt^T + bias) ----------------
// ytile0: M-tile offset, so halves of the M range can run on different streams.
template <int NFRAG, int OUT_HALF, int RELU, int WRITE_HS>
__global__ void __launch_bounds__(256, 2)
gemm_tma(const __grid_constant__ CUtensorMap mA, const __grid_constant__ CUtensorMap mB,
         const float* __restrict__ bias, float* __restrict__ Cf, __half* __restrict__ Ch,
         const float* __restrict__ normp, __half* __restrict__ Hs,
         int M, int K, int Nout, int ytile0) {
    constexpr int BN = NFRAG * 16;
    constexpr int WN = NFRAG * 8;
    constexpr int ABYT = 128 * 64 * 2;
    constexpr int BBYT = BN * 64 * 2;
    constexpr int STAGE = ABYT + BBYT;

    extern __shared__ __align__(1024) char dsm[];
    __shared__ __align__(8) unsigned long long s_bar[NS];

    const int tid = threadIdx.x, lane = tid & 31, wid = tid >> 5;
    const int wm = wid & 3, wn = wid >> 2;
    const int m0 = (blockIdx.y + ytile0) * 128, n0 = blockIdx.x * BN;
    const uint32_t sb = smem_to_u32(dsm);
    const uint32_t bar = smem_to_u32(s_bar);
    const int NKT = K >> 6;

    if (tid == 0) {
#pragma unroll
        for (int i = 0; i < NS; i++) MBARRIER_INIT(bar + 8 * i, 1);
    }
    __syncthreads();

    if (tid == 0) {
        for (int s = 0; s < NS && s < NKT; s++) {
            uint32_t sa = sb + s * STAGE;
            uint32_t mb = bar + 8 * s;
            MBARRIER_EXPECT_TX(mb, (uint32_t)STAGE);
            TMA_LOAD_2D(sa, &mA, s * 64, m0, mb);
            TMA_LOAD_2D(sa + ABYT, &mB, s * 64, n0, mb);
        }
    }

    float acc[2][NFRAG][4];
#pragma unroll
    for (int a = 0; a < 2; a++)
#pragma unroll
        for (int b = 0; b < NFRAG; b++)
#pragma unroll
            for (int c = 0; c < 4; c++) acc[a][b][c] = 0.f;

    const int csel = (lane >> 4) << 3;
    const int rsub = lane & 15;

    for (int i = 0; i < NKT; i++) {
        int s = i - (i / NS) * NS;
        MBARRIER_WAIT_PARITY(bar + 8 * s, (i / NS) & 1);
        uint32_t aB = sb + s * STAGE;
        uint32_t bB = aB + ABYT;
#pragma unroll
        for (int kc = 0; kc < 4; kc++) {
            int cc = kc * 16 + csel;
            int chunk = cc >> 3;
            uint32_t a[2][4];
#pragma unroll
            for (int mt = 0; mt < 2; mt++) {
                int r = wm * 32 + mt * 16 + rsub;
                uint32_t off = (uint32_t)(r * 128 + ((chunk ^ (r & 7)) << 4));
                LDSM4(a[mt][0], a[mt][1], a[mt][2], a[mt][3], aB + off);
            }
            uint32_t bfr[NFRAG][2];
#pragma unroll
            for (int p = 0; p < NFRAG / 2; p++) {
                int r = wn * WN + p * 16 + rsub;
                uint32_t off = (uint32_t)(r * 128 + ((chunk ^ (r & 7)) << 4));
                uint32_t r0, r1, r2, r3;
                LDSM4(r0, r1, r2, r3, bB + off);
                bfr[2 * p][0] = r0; bfr[2 * p][1] = r2;
                bfr[2 * p + 1][0] = r1; bfr[2 * p + 1][1] = r3;
            }
#pragma unroll
            for (int mt = 0; mt < 2; mt++)
#pragma unroll
                for (int nt = 0; nt < NFRAG; nt++)
                    MMAF16(acc[mt][nt], a[mt], bfr[nt][0], bfr[nt][1]);
        }
        __syncthreads();
        if (tid == 0 && i + NS < NKT) {
            int kx = (i + NS) * 64;
            uint32_t sa = sb + s * STAGE;
            uint32_t mb = bar + 8 * s;
            MBARRIER_EXPECT_TX(mb, (uint32_t)STAGE);
            TMA_LOAD_2D(sa, &mA, kx, m0, mb);
            TMA_LOAD_2D(sa + ABYT, &mB, kx, n0, mb);
        }
    }

    // ---- epilogue ----
    const int g = lane >> 2, tq = (lane & 3) << 1;
#pragma unroll
    for (int mt = 0; mt < 2; mt++) {
        int r = m0 + wm * 32 + mt * 16 + g;
        float nn0 = 0.f, nn1 = 0.f;
        if (WRITE_HS) {
            if (r < M) nn0 = normp[r];
            if (r + 8 < M) nn1 = normp[r + 8];
        }
#pragma unroll
        for (int nt = 0; nt < NFRAG; nt++) {
            int cb = n0 + wn * WN + nt * 8 + tq;
            float b0v = __ldg(bias + cb), b1v = __ldg(bias + cb + 1);
            float v0 = acc[mt][nt][0] + b0v, v1 = acc[mt][nt][1] + b1v;
            float v2 = acc[mt][nt][2] + b0v, v3 = acc[mt][nt][3] + b1v;
            if (RELU) {
                v0 = fmaxf(v0, 0.f); v1 = fmaxf(v1, 0.f);
                v2 = fmaxf(v2, 0.f); v3 = fmaxf(v3, 0.f);
            }
            if (OUT_HALF) {
                if (r < M) {
                    __half2 hp = __floats2half2_rn(v0, v1);
                    *(uint32_t*)(Ch + (size_t)r * Nout + cb) = *(uint32_t*)&hp;
                }
                if (r + 8 < M) {
                    __half2 hp = __floats2half2_rn(v2, v3);
                    *(uint32_t*)(Ch + (size_t)(r + 8) * Nout + cb) = *(uint32_t*)&hp;
                }
            } else {
                if (r < M) {
                    *(float2*)(Cf + (size_t)r * Nout + cb) = make_float2(v0, v1);
                    if (WRITE_HS) {
                        __half2 hp = __floats2half2_rn(v0 * nn0, v1 * nn0);
                        *(uint32_t*)(Hs + (size_t)r * Nout + cb) = *(uint32_t*)&hp;
                    }
                }
                if (r + 8 < M) {
                    *(float2*)(Cf + (size_t)(r + 8) * Nout + cb) = make_float2(v2, v3);
                    if (WRITE_HS) {
                        __half2 hp = __floats2half2_rn(v2 * nn1, v3 * nn1);
                        *(uint32_t*)(Hs + (size_t)(r + 8) * Nout + cb) = *(uint32_t*)&hp;
                    }
                }
            }
        }
    }
}

// ---------------- propagation (fp16 state, per-iteration launches) ----------------
__global__ void prop_kernel(const __half* __restrict__ hs, const float* __restrict__ h0,
                            const float* __restrict__ norm, const int* __restrict__ rowptr,
                            const int* __restrict__ col, __half* __restrict__ outh,
                            float* __restrict__ outf, int n, int last) {
    int gt = blockIdx.x * blockDim.x + threadIdx.x;
    int lane = threadIdx.x & 31;
    int node = ((gt >> 5) << 2) + (lane >> 3);
    if (node >= n) return;
    int l8 = lane & 7;
    int beg = __ldg(rowptr + node), end = __ldg(rowptr + node + 1);
    float a0 = 0.f, a1 = 0.f, a2 = 0.f, a3 = 0.f, a4 = 0.f, a5 = 0.f, a6 = 0.f, a7 = 0.f;
    int j = beg;
    for (; j + 2 <= end; j += 2) {
        int s0 = __ldg(col + j), s1 = __ldg(col + j + 1);
        uint4 v = __ldg((const uint4*)(hs + (size_t)s0 * N_CLASSES + l8 * 8));
        uint4 w = __ldg((const uint4*)(hs + (size_t)s1 * N_CLASSES + l8 * 8));
        float2 f0 = __half22float2(*(__half2*)&v.x);
        float2 f1 = __half22float2(*(__half2*)&v.y);
        float2 f2 = __half22float2(*(__half2*)&v.z);
        float2 f3 = __half22float2(*(__half2*)&v.w);
        float2 g0 = __half22float2(*(__half2*)&w.x);
        float2 g1 = __half22float2(*(__half2*)&w.y);
        float2 g2 = __half22float2(*(__half2*)&w.z);
        float2 g3 = __half22float2(*(__half2*)&w.w);
        a0 += f0.x + g0.x; a1 += f0.y + g0.y;
        a2 += f1.x + g1.x; a3 += f1.y + g1.y;
        a4 += f2.x + g2.x; a5 += f2.y + g2.y;
        a6 += f3.x + g3.x; a7 += f3.y + g3.y;
    }
    if (j < end) {
        uint4 v = __ldg((const uint4*)(hs + (size_t)__ldg(col + j) * N_CLASSES + l8 * 8));
        float2 f0 = __half22float2(*(__half2*)&v.x);
        float2 f1 = __half22float2(*(__half2*)&v.y);
        float2 f2 = __half22float2(*(__half2*)&v.z);
        float2 f3 = __half22float2(*(__half2*)&v.w);
        a0 += f0.x; a1 += f0.y; a2 += f1.x; a3 += f1.y;
        a4 += f2.x; a5 += f2.y; a6 += f3.x; a7 += f3.y;
    }
    float nn = norm[node];
    const float* hp = h0 + (size_t)node * N_CLASSES + l8 * 8;
    float4 hA = *(const float4*)hp;
    float4 hB = *(const float4*)(hp + 4);
    float o0 = (1.0f - ALPHA_F) * a0 * nn + ALPHA_F * hA.x;
    float o1 = (1.0f - ALPHA_F) * a1 * nn + ALPHA_F * hA.y;
    float o2 = (1.0f - ALPHA_F) * a2 * nn + ALPHA_F * hA.z;
    float o3 = (1.0f - ALPHA_F) * a3 * nn + ALPHA_F * hA.w;
    float o4 = (1.0f - ALPHA_F) * a4 * nn + ALPHA_F * hB.x;
    float o5 = (1.0f - ALPHA_F) * a5 * nn + ALPHA_F * hB.y;
    float o6 = (1.0f - ALPHA_F) * a6 * nn + ALPHA_F * hB.z;
    float o7 = (1.0f - ALPHA_F) * a7 * nn + ALPHA_F * hB.w;
    if (last) {
        float* op = outf + (size_t)node * N_CLASSES + l8 * 8;
        *(float4*)op = make_float4(o0, o1, o2, o3);
        *(float4*)(op + 4) = make_float4(o4, o5, o6, o7);
    } else {
        __half2 p0 = __floats2half2_rn(o0 * nn, o1 * nn);
        __half2 p1 = __floats2half2_rn(o2 * nn, o3 * nn);
        __half2 p2 = __floats2half2_rn(o4 * nn, o5 * nn);
        __half2 p3 = __floats2half2_rn(o6 * nn, o7 * nn);
        uint4 w = make_uint4(*(uint32_t*)&p0, *(uint32_t*)&p1,
                             *(uint32_t*)&p2, *(uint32_t*)&p3);
        *(uint4*)(outh + (size_t)node * N_CLASSES + l8 * 8) = w;
    }
}

// ---------------- host: tensormap + launch ----------------
typedef CUresult (*EncodeFn)(CUtensorMap*, CUtensorMapDataType, cuuint32_t, void*,
                             const cuuint64_t*, const cuuint64_t*, const cuuint32_t*,
                             const cuuint32_t*, CUtensorMapInterleave, CUtensorMapSwizzle,
                             CUtensorMapL2promotion, CUtensorMapFloatOOBfill);

static void make_map(EncodeFn enc, CUtensorMap* m, void* base, uint64_t d0, uint64_t d1,
                     uint32_t b0, uint32_t b1) {
    cuuint64_t dims[2] = {d0, d1};
    cuuint64_t strides[1] = {d0 * 2};
    cuuint32_t box[2] = {b0, b1};
    cuuint32_t es[2] = {1, 1};
    enc(m, CU_TENSOR_MAP_DATA_TYPE_FLOAT16, 2, base, dims, strides, box, es,
        CU_TENSOR_MAP_INTERLEAVE_NONE, CU_TENSOR_MAP_SWIZZLE_128B,
        CU_TENSOR_MAP_L2_PROMOTION_L2_128B, CU_TENSOR_MAP_FLOAT_OOB_FILL_NONE);
}

extern "C" void kernel_launch(void* const* d_in, const int* in_sizes, int n_in,
                              void* d_out, int out_size) {
    const float* features = (const float*)d_in[0];
    const void*  src = d_in[1];
    const void*  dst = d_in[2];
    const float* W0 = (const float*)d_in[3];
    const float* b0 = (const float*)d_in[4];
    const float* W1 = (const float*)d_in[5];
    const float* b1 = (const float*)d_in[6];
    const float* W2 = (const float*)d_in[7];
    const float* b2 = (const float*)d_in[8];
    float* out = (float*)d_out;
    const int Nn = in_sizes[0] / IN_FEATS;
    const int E  = in_sizes[1];

    void *p_fh, *p_h1h, *p_h2h, *p_w0, *p_w1, *p_w2, *p_hsA, *p_hsB;
    float *p_h0, *p_norm;
    int *p_deg, *p_rowptr, *p_fill, *p_col;
    cudaGetSymbolAddress(&p_fh, g_fh);
    cudaGetSymbolAddress(&p_h1h, g_h1h);
    cudaGetSymbolAddress(&p_h2h, g_h2h);
    cudaGetSymbolAddress(&p_w0, g_w0);
    cudaGetSymbolAddress(&p_w1, g_w1);
    cudaGetSymbolAddress(&p_w2, g_w2);
    cudaGetSymbolAddress(&p_hsA, g_hsA);
    cudaGetSymbolAddress(&p_hsB, g_hsB);
    cudaGetSymbolAddress((void**)&p_h0, g_h0);
    cudaGetSymbolAddress((void**)&p_norm, g_norm);
    cudaGetSymbolAddress((void**)&p_deg, g_deg);
    cudaGetSymbolAddress((void**)&p_rowptr, g_rowptr);
    cudaGetSymbolAddress((void**)&p_fill, g_fill);
    cudaGetSymbolAddress((void**)&p_col, g_col);

    EncodeFn enc = nullptr;
    cudaDriverEntryPointQueryResult qst;
    cudaGetDriverEntryPointByVersion("cuTensorMapEncodeTiled", (void**)&enc, 12000,
                                     cudaEnableDefault, &qst);

    CUtensorMap mF, mH1, mH2, mW0, mW1, mW2;
    make_map(enc, &mF, p_fh, IN_FEATS, Nn, 64, 128);
    make_map(enc, &mH1, p_h1h, N_HIDDEN, Nn, 64, 128);
    make_map(enc, &mH2, p_h2h, N_HIDDEN, Nn, 64, 128);
    make_map(enc, &mW0, p_w0, IN_FEATS, N_HIDDEN, 64, 128);
    make_map(enc, &mW1, p_w1, N_HIDDEN, N_HIDDEN, 64, 128);
    make_map(enc, &mW2, p_w2, N_HIDDEN, N_CLASSES, 64, 64);

    const int STG8 = 16384 + 128 * 64 * 2;   // 32768
    const int STG4 = 16384 + 64 * 64 * 2;    // 24576
    const int SM8 = NS * STG8;                // 98304 -> 2 CTAs/SM
    const int SM4 = NS * STG4;                // 73728
    cudaFuncSetAttribute(gemm_tma<8, 1, 1, 0>, cudaFuncAttributeMaxDynamicSharedMemorySize, SM8);
    cudaFuncSetAttribute(gemm_tma<4, 0, 0, 1>, cudaFuncAttributeMaxDynamicSharedMemorySize, SM4);

    // M-halves
    const int mtiles = (Nn + 127) / 128;
    const int mt0 = (mtiles + 1) / 2;         // first-half tiles
    const int mt1 = mtiles - mt0;
    const int rows0 = mt0 * 128;              // rows in half 0 (<= Nn)
    const int n4_total = Nn * IN_FEATS / 4;
    const int n4_h0 = min(rows0 * IN_FEATS / 4, n4_total);
    const int n4_h1 = n4_total - n4_h0;

    // ---- streams: side1=CSR, side2=W1/W2 converts, side3=half-1 MLP chain ----
    cudaStream_t side1, side2, side3;
    cudaStreamCreate(&side1);
    cudaStreamCreate(&side2);
    cudaStreamCreate(&side3);
    cudaEvent_t evFork, evJoin1, evJoin2, evW0, evH1done;
    cudaEventCreate(&evFork);
    cudaEventCreate(&evJoin1);
    cudaEventCreate(&evJoin2);
    cudaEventCreate(&evW0);
    cudaEventCreate(&evH1done);
    cudaEventRecord(evFork, 0);
    cudaStreamWaitEvent(side1, evFork, 0);
    cudaStreamWaitEvent(side2, evFork, 0);
    cudaStreamWaitEvent(side3, evFork, 0);

    // side1: CSR build
    detect_kernel<<<1, 256, 0, side1>>>((const int*)dst, E);
    cudaMemsetAsync(p_deg, 0, Nn * sizeof(int), side1);
    count_deg_kernel<<<(E + 255) / 256, 256, 0, side1>>>(dst, p_deg, E);
    scan_kernel<<<1, 1024, 0, side1>>>(p_deg, p_rowptr, p_fill, p_norm, Nn, E);
    fill_csr_kernel<<<(E + 255) / 256, 256, 0, side1>>>(src, dst, p_fill, p_col, E);
    cudaEventRecord(evJoin1, side1);

    // side2: W1/W2 converts
    wconv_kernel<<<(N_HIDDEN * N_HIDDEN + 255) / 256, 256, 0, side2>>>(
        W1, (__half*)p_w1, N_HIDDEN, N_HIDDEN);
    wconv_kernel<<<(N_HIDDEN * N_CLASSES + 255) / 256, 256, 0, side2>>>(
        W2, (__half*)p_w2, N_HIDDEN, N_CLASSES);
    cudaEventRecord(evJoin2, side2);

    // main (stream 0): W0 convert + fconv half 0
    wconv_kernel<<<(IN_FEATS * N_HIDDEN + 255) / 256, 256>>>(
        W0, (__half*)p_w0, IN_FEATS, N_HIDDEN);
    cudaEventRecord(evW0, 0);
    fconv_kernel<<<(n4_h0 + 255) / 256, 256>>>(features, (__half*)p_fh, n4_h0);

    // side3: fconv half 1 (waits for W0 before its GEMM1)
    if (n4_h1 > 0)
        fconv_kernel<<<(n4_h1 + 255) / 256, 256, 0, side3>>>(
            features + (size_t)n4_h0 * 4, (__half*)p_fh + (size_t)n4_h0 * 4, n4_h1);
    cudaStreamWaitEvent(side3, evW0, 0);

    // ---- MLP chains, halved across streams ----
    {   // GEMM1
        dim3 g0(N_HIDDEN / 128, mt0), g1(N_HIDDEN / 128, mt1 > 0 ? mt1 : 1);
        gemm_tma<8, 1, 1, 0><<<g0, 256, SM8>>>(
            mF, mW0, b0, nullptr, (__half*)p_h1h, nullptr, nullptr, Nn, IN_FEATS, N_HIDDEN, 0);
        if (mt1 > 0)
            gemm_tma<8, 1, 1, 0><<<g1, 256, SM8, side3>>>(
                mF, mW0, b0, nullptr, (__half*)p_h1h, nullptr, nullptr, Nn, IN_FEATS, N_HIDDEN, mt0);
    }
    cudaStreamWaitEvent(0, evJoin2, 0);
    cudaStreamWaitEvent(side3, evJoin2, 0);
    {   // GEMM2
        dim3 g0(N_HIDDEN / 128, mt0), g1(N_HIDDEN / 128, mt1 > 0 ? mt1 : 1);
        gemm_tma<8, 1, 1, 0><<<g0, 256, SM8>>>(
            mH1, mW1, b1, nullptr, (__half*)p_h2h, nullptr, nullptr, Nn, N_HIDDEN, N_HIDDEN, 0);
        if (mt1 > 0)
            gemm_tma<8, 1, 1, 0><<<g1, 256, SM8, side3>>>(
                mH1, mW1, b1, nullptr, (__half*)p_h2h, nullptr, nullptr, Nn, N_HIDDEN, N_HIDDEN, mt0);
    }
    cudaStreamWaitEvent(0, evJoin1, 0);
    cudaStreamWaitEvent(side3, evJoin1, 0);
    {   // GEMM3 (+ fused hs init)
        dim3 g0(1, mt0), g1(1, mt1 > 0 ? mt1 : 1);
        gemm_tma<4, 0, 0, 1><<<g0, 256, SM4>>>(
            mH2, mW2, b2, p_h0, nullptr, p_norm, (__half*)p_hsA, Nn, N_HIDDEN, N_CLASSES, 0);
        if (mt1 > 0)
            gemm_tma<4, 0, 0, 1><<<g1, 256, SM4, side3>>>(
                mH2, mW2, b2, p_h0, nullptr, p_norm, (__half*)p_hsA, Nn, N_HIDDEN, N_CLASSES, mt0);
    }
    cudaEventRecord(evH1done, side3);
    cudaStreamWaitEvent(0, evH1done, 0);   // prop needs full hsA

    // ---- propagation: per-iteration launches ----
    const __half* cur = (const __half*)p_hsA;
    for (int it = 0; it < K_ITERS; it++) {
        int last = (it == K_ITERS - 1) ? 1 : 0;
        __half* oh = (it & 1) ? (__half*)p_hsA : (__half*)p_hsB;
        int blocks = (Nn * 8 + 255) / 256;
        prop_kernel<<<blocks, 256>>>(cur, p_h0, p_norm, p_rowptr, p_col, oh, out, Nn, last);
        cur = oh;
    }

    cudaEventDestroy(evFork);
    cudaEventDestroy(evJoin1);
    cudaEventDestroy(evJoin2);
    cudaEventDestroy(evW0);
    cudaEventDestroy(evH1done);
    cudaStreamDestroy(side1);
    cudaStreamDestroy(side2);
    cudaStreamDestroy(side3);
}